// round 2
// baseline (speedup 1.0000x reference)
#include <cuda_runtime.h>
#include <math.h>

#define HID 64
#define NMAX 8192
#define EMAX 131072

// ---------------- device scratch (no allocation allowed) ----------------
__device__ float g_Jv[EMAX];        // J[row,col] per edge
__device__ float g_Cij[EMAX];       // Cij_e per edge
__device__ float g_jc[EMAX];        // Jv / Cij_e per edge
__device__ float g_emA[2 * EMAX];   // edge messages ping
__device__ float g_emB[2 * EMAX];   // edge messages pong
__device__ float g_f1[NMAX];
__device__ float g_f2[NMAX];
__device__ float g_Ci[NMAX];
__device__ float g_dom[NMAX];
__device__ float g_bx[2 * NMAX];
__device__ float g_hidden[2 * NMAX];
__device__ float g_lnZ[NMAX];
__device__ int   g_start[NMAX + 1]; // CSR row starts (degree from sorted `row`)
__device__ float g_npart[128];      // node-entropy block partials
__device__ float g_epart[512];      // edge-entropy block partials

// ---------------- kernel 1: per-edge init (Jv gather, CSR starts, em0=0) ----
__global__ void k_edge_init(const float* __restrict__ J,
                            const int* __restrict__ row,
                            const int* __restrict__ col,
                            int N, int E) {
    int e = blockIdx.x * blockDim.x + threadIdx.x;
    if (e >= E) return;
    int r = row[e];
    int c = col[e];
    g_Jv[e] = J[(long long)r * N + c];
    g_emA[2 * e]     = 0.0f;
    g_emA[2 * e + 1] = 0.0f;
    if (e == 0 || row[e - 1] != r) g_start[r] = e;
    if (e == E - 1) g_start[N] = E;
}

// ---------------- kernel 2: node features + GAT scores f1/f2 + Ci MLP ------
// 256 threads = 4 nodes/block, unit = tid & 63. W2 (64x64) staged in smem.
__global__ __launch_bounds__(256)
void k_node_mlp(const float* __restrict__ bias,
                const float* __restrict__ gat_W, const float* __restrict__ gat_a,
                const float* __restrict__ W1, const float* __restrict__ b1,
                const float* __restrict__ W2, const float* __restrict__ b2,
                const float* __restrict__ W3, const float* __restrict__ b3,
                float* __restrict__ out_Ci, int N) {
    __shared__ float sW2[HID * HID];
    __shared__ float sh1[4][HID];
    __shared__ float sr[4][2][3];   // [node_local][warp-half][f1,f2,ci]

    int t = threadIdx.x;
    for (int i = t; i < HID * HID; i += blockDim.x) sW2[i] = W2[i];

    int nl = t >> 6;
    int u  = t & 63;
    int node = blockIdx.x * 4 + nl;
    int nc = node < N ? node : N - 1;

    float b = bias[nc];
    int s0 = g_start[nc], s1 = g_start[nc + 1];
    float deg = (float)(s1 - s0);
    float Jsum = 0.0f;
    for (int k = s0; k < s1; k++) Jsum += g_Jv[k];
    float ft0 = -b, ft1 = b, ft2 = deg, ft3 = Jsum;

    // GAT: Wh[u] then reduce Wh*a over the 64 units of this node
    float wh = ft0 * gat_W[u] + ft1 * gat_W[HID + u]
             + ft2 * gat_W[2 * HID + u] + ft3 * gat_W[3 * HID + u];
    float c1 = wh * gat_a[u];
    float c2 = wh * gat_a[HID + u];

    // Ci MLP layer 1
    float h1 = b1[u] + ft0 * W1[u] + ft1 * W1[HID + u]
             + ft2 * W1[2 * HID + u] + ft3 * W1[3 * HID + u];
    h1 = fmaxf(h1, 0.0f);
    sh1[nl][u] = h1;

    #pragma unroll
    for (int off = 16; off > 0; off >>= 1) {
        c1 += __shfl_down_sync(0xffffffffu, c1, off);
        c2 += __shfl_down_sync(0xffffffffu, c2, off);
    }
    int half = (u >> 5);
    if ((u & 31) == 0) { sr[nl][half][0] = c1; sr[nl][half][1] = c2; }
    __syncthreads();   // covers sW2, sh1, sr

    if (node < N && u == 0) {
        g_f1[node] = sr[nl][0][0] + sr[nl][1][0];
        g_f2[node] = sr[nl][0][1] + sr[nl][1][1];
    }

    // Ci MLP layer 2 + readout
    float h2 = b2[u];
    #pragma unroll 8
    for (int k = 0; k < HID; k++) h2 += sh1[nl][k] * sW2[k * HID + u];
    h2 = fmaxf(h2, 0.0f);
    float cp = h2 * W3[u];
    #pragma unroll
    for (int off = 16; off > 0; off >>= 1)
        cp += __shfl_down_sync(0xffffffffu, cp, off);
    if ((u & 31) == 0) sr[nl][half][2] = cp;
    __syncthreads();

    if (node < N && u == 0) {
        float Ci = sr[nl][0][2] + sr[nl][1][2] + b3[0];
        g_Ci[node] = Ci;
        out_Ci[node] = Ci;
    }
}

// ---------------- kernel 3: per-edge attention Cij and J/Cij ---------------
__global__ void k_edge_cij(const int* __restrict__ row,
                           const int* __restrict__ col, int E) {
    int e = blockIdx.x * blockDim.x + threadIdx.x;
    if (e >= E) return;
    int r = row[e], c = col[e];
    float a = g_f1[r] + g_f2[c];
    float b = g_f1[c] + g_f2[r];
    a = (a >= 0.0f) ? a : 0.2f * a;     // leaky_relu 0.2
    b = (b >= 0.0f) ? b : 0.2f * b;
    float cij = 0.5f * (expf(a) + expf(b));
    g_Cij[e] = cij;
    g_jc[e]  = g_Jv[e] / cij;
}

// ---------------- kernel 4: dom clamp, bx_scale, initial node_update -------
__global__ void k_node_dom(const float* __restrict__ bias,
                           float* __restrict__ out_dom, int N) {
    int i = blockIdx.x * blockDim.x + threadIdx.x;
    if (i >= N) return;
    int s0 = g_start[i], s1 = g_start[i + 1];
    float csum = 0.0f;
    for (int k = s0; k < s1; k++) csum += g_Cij[k];
    float dom = g_Ci[i] + csum;
    float sgn = (dom > 0.0f) ? 1.0f : ((dom < 0.0f) ? -1.0f : 0.0f);
    float domc = sgn * fmaxf(fabsf(dom), 0.1f);
    g_dom[i] = domc;
    out_dom[i] = domc;
    float bs  = bias[i] / domc;
    float bx0 = -bs, bx1 = bs;
    g_bx[2 * i] = bx0;
    g_bx[2 * i + 1] = bx1;
    float lnZ = logf(expf(bx0) + expf(bx1));   // nm == 0 at step 0
    g_lnZ[i] = lnZ;
    g_hidden[2 * i]     = bx0 - lnZ;
    g_hidden[2 * i + 1] = bx1 - lnZ;
}

// ---------------- kernel 5: BP edge message ---------------------------------
// M[x][y] = exp(±jc + hidden[row,x] + lnZ[row] - em_rev[x]); normalize by
// sum_y max_x; em_new[y] = Cij * log(max_x M[x][y]).
__global__ void k_bp_edge(const int* __restrict__ row,
                          const int* __restrict__ rev,
                          int flip, int E) {
    int e = blockIdx.x * blockDim.x + threadIdx.x;
    if (e >= E) return;
    const float* emIn = flip ? g_emB : g_emA;
    float*       emOut = flip ? g_emA : g_emB;
    int r  = row[e];
    int re = rev[e];
    float h0 = g_hidden[2 * r], h1 = g_hidden[2 * r + 1];
    float lz = g_lnZ[r];
    float mu0 = emIn[2 * re], mu1 = emIn[2 * re + 1];
    float jc  = g_jc[e];
    float b0 = h0 + lz - mu0;
    float b1 = h1 + lz - mu1;
    float M00 = expf( jc + b0);
    float M01 = expf(-jc + b0);
    float M10 = expf(-jc + b1);
    float M11 = expf( jc + b1);
    float t0 = fmaxf(M00, M10);
    float t1 = fmaxf(M01, M11);
    float denom = t0 + t1;
    float C = g_Cij[e];
    emOut[2 * e]     = C * logf(t0 / denom);
    emOut[2 * e + 1] = C * logf(t1 / denom);
}

// ---------------- kernel 6: BP node update ----------------------------------
// incoming edges of j = rev[out-edges of j] — already in JAX segment order.
__global__ void k_bp_node(const int* __restrict__ rev, int flip, int N) {
    int j = blockIdx.x * blockDim.x + threadIdx.x;
    if (j >= N) return;
    const float* em = flip ? g_emA : g_emB;   // buffer just written by k_bp_edge
    int s0 = g_start[j], s1 = g_start[j + 1];
    float nm0 = 0.0f, nm1 = 0.0f;
    for (int k = s0; k < s1; k++) {
        int e2 = rev[k];
        nm0 += em[2 * e2];
        nm1 += em[2 * e2 + 1];
    }
    float d = g_dom[j];
    nm0 /= d; nm1 /= d;
    float x0 = g_bx[2 * j] + nm0;
    float x1 = g_bx[2 * j + 1] + nm1;
    float lnZ = logf(expf(x0) + expf(x1));
    g_lnZ[j] = lnZ;
    g_hidden[2 * j]     = x0 - lnZ;
    g_hidden[2 * j + 1] = x1 - lnZ;
}

// ---------------- kernel 7: readout + node entropy partials -----------------
__global__ __launch_bounds__(128)
void k_readout(float* __restrict__ out_readout, int N) {
    __shared__ float sred[128];
    int i = blockIdx.x * blockDim.x + threadIdx.x;
    float p = 0.0f;
    if (i < N) {
        float r0 = expf(g_hidden[2 * i]);
        float r1 = expf(g_hidden[2 * i + 1]);
        out_readout[2 * i]     = r0;
        out_readout[2 * i + 1] = r1;
        float nH = -(r0 * logf(r0 + 1e-16f) + r1 * logf(r1 + 1e-16f));
        p = g_Ci[i] * nH;
    }
    sred[threadIdx.x] = p;
    __syncthreads();
    #pragma unroll
    for (int off = 64; off > 0; off >>= 1) {
        if (threadIdx.x < off) sred[threadIdx.x] += sred[threadIdx.x + off];
        __syncthreads();
    }
    if (threadIdx.x == 0) g_npart[blockIdx.x] = sred[0];
}

// ---------------- kernel 8: pairwise readout + edge entropy partials --------
__global__ __launch_bounds__(128)
void k_pair(const int* __restrict__ ru, const int* __restrict__ cu,
            const int* __restrict__ u2e, const int* __restrict__ rev,
            const float* __restrict__ readout,
            float* __restrict__ out_pw, float* __restrict__ out_cij,
            int femA, int Eu) {
    __shared__ float sred[128];
    int u = blockIdx.x * blockDim.x + threadIdx.x;
    float p = 0.0f;
    if (u < Eu) {
        const float* em = femA ? g_emA : g_emB;
        int e  = u2e[u];
        int er = rev[e];
        int ci = cu[u], rj = ru[u];
        float Js  = g_jc[e];
        float ti0 = readout[2 * ci]     / expf(em[2 * e]);
        float ti1 = readout[2 * ci + 1] / expf(em[2 * e + 1]);
        float tj0 = readout[2 * rj]     / expf(em[2 * er]);
        float tj1 = readout[2 * rj + 1] / expf(em[2 * er + 1]);
        float eJ  = expf(Js);
        float eJm = expf(-Js);
        float p00 = eJ  * ti0 * tj0;   // (x=0,y=0)
        float p01 = eJm * ti1 * tj0;   // (x=0,y=1)
        float p10 = eJm * ti0 * tj1;   // (x=1,y=0)
        float p11 = eJ  * ti1 * tj1;   // (x=1,y=1)
        float S = p00 + p01 + p10 + p11;
        float q00 = p00 / S, q01 = p01 / S, q10 = p10 / S, q11 = p11 / S;
        out_pw[4 * u]     = q00;
        out_pw[4 * u + 1] = q01;
        out_pw[4 * u + 2] = q10;
        out_pw[4 * u + 3] = q11;
        float Cu = g_Cij[e];
        out_cij[u] = Cu;
        float eH = -(q00 * logf(q00 + 1e-16f) + q01 * logf(q01 + 1e-16f)
                   + q10 * logf(q10 + 1e-16f) + q11 * logf(q11 + 1e-16f));
        p = Cu * eH;
    }
    sred[threadIdx.x] = p;
    __syncthreads();
    #pragma unroll
    for (int off = 64; off > 0; off >>= 1) {
        if (threadIdx.x < off) sred[threadIdx.x] += sred[threadIdx.x + off];
        __syncthreads();
    }
    if (threadIdx.x == 0) g_epart[blockIdx.x] = sred[0];
}

// ---------------- kernel 9: final deterministic scalar sums -----------------
__global__ void k_final(float* __restrict__ out_scal, int nbN, int nbE) {
    if (threadIdx.x != 0 || blockIdx.x != 0) return;
    float ne = 0.0f;
    for (int b = 0; b < nbN; b++) ne += g_npart[b];
    float ee = 0.0f;
    for (int b = 0; b < nbE; b++) ee += g_epart[b];
    out_scal[0] = ne + ee;
    out_scal[1] = ne;
    out_scal[2] = ee;
}

// ---------------- launcher ---------------------------------------------------
extern "C" void kernel_launch(void* const* d_in, const int* in_sizes, int n_in,
                              void* d_out, int out_size) {
    const float* J     = (const float*)d_in[0];
    const float* bias  = (const float*)d_in[1];
    const float* gat_W = (const float*)d_in[2];
    const float* gat_a = (const float*)d_in[3];
    const float* W1    = (const float*)d_in[4];
    const float* b1    = (const float*)d_in[5];
    const float* W2    = (const float*)d_in[6];
    const float* b2    = (const float*)d_in[7];
    const float* W3    = (const float*)d_in[8];
    const float* b3    = (const float*)d_in[9];
    const int*   row   = (const int*)d_in[10];
    const int*   col   = (const int*)d_in[11];
    const int*   rev   = (const int*)d_in[12];
    const int*   ru    = (const int*)d_in[13];
    const int*   cu    = (const int*)d_in[14];
    const int*   u2e   = (const int*)d_in[15];

    int N  = in_sizes[1];
    int E  = in_sizes[10];
    int Eu = in_sizes[13];
    const int NSTEP = 10;

    float* out = (float*)d_out;
    float* out_readout = out;                    // [N,2]
    float* out_pw      = out + 2 * N;            // [Eu,4]
    float* out_scal    = out + 2 * N + 4 * Eu;   // 3 scalars
    float* out_Ci      = out_scal + 3;           // [N]
    float* out_cij     = out_Ci + N;             // [Eu]
    float* out_dom     = out_cij + Eu;           // [N]

    int ebl = (E + 255) / 256;
    int nbl = (N + 255) / 256;

    k_edge_init<<<ebl, 256>>>(J, row, col, N, E);
    k_node_mlp<<<(N + 3) / 4, 256>>>(bias, gat_W, gat_a, W1, b1, W2, b2, W3, b3,
                                     out_Ci, N);
    k_edge_cij<<<ebl, 256>>>(row, col, E);
    k_node_dom<<<nbl, 256>>>(bias, out_dom, N);

    int flip = 0;  // current em lives in A when flip==0
    for (int t = 0; t < NSTEP; t++) {
        k_bp_edge<<<ebl, 256>>>(row, rev, flip, E);
        k_bp_node<<<nbl, 256>>>(rev, flip, N);
        flip ^= 1;
    }
    int femA = (NSTEP % 2 == 0) ? 1 : 0;  // final em buffer after even #steps: A

    int nbN = (N + 127) / 128;
    int nbE = (Eu + 127) / 128;
    k_readout<<<nbN, 128>>>(out_readout, N);
    k_pair<<<nbE, 128>>>(ru, cu, u2e, rev, out_readout, out_pw, out_cij, femA, Eu);
    k_final<<<1, 32>>>(out_scal, nbN, nbE);
}

// round 3
// speedup vs baseline: 1.7814x; 1.7814x over previous
#include <cuda_runtime.h>
#include <math.h>

#define HID 64
#define NMAX 8192
#define EMAX 131072
#define NBLK 128
#define NTHR 512
#define MAXEPT 2
#define NSTEP 10

// ---------------- device scratch (no allocation allowed) ----------------
__device__ float g_Jv[EMAX];
__device__ float g_Cij[EMAX];
__device__ float g_jc[EMAX];
__device__ float g_emA[2 * EMAX];
__device__ float g_emB[2 * EMAX];
__device__ float g_f1[NMAX];
__device__ float g_f2[NMAX];
__device__ float g_Ci[NMAX];
__device__ float g_hidden[2 * NMAX];
__device__ float g_lnZ[NMAX];
__device__ int   g_start[NMAX + 1];
__device__ float g_npart[NBLK];
__device__ float g_epart[NBLK];
__device__ unsigned g_count;   // zero-init; returns to 0 every launch
__device__ unsigned g_sense;   // zero-init; 14 (even) flips per launch -> back to 0

// Sense-reversal grid barrier. gpu-scope __threadfence emits CCTL.IVALL on
// sm_103a -> L1D flushed, so plain loads after the barrier see remote writes.
__device__ __forceinline__ void grid_barrier(unsigned& lsense) {
    __syncthreads();
    if (threadIdx.x == 0) {
        unsigned s = lsense ^ 1u;
        lsense = s;
        __threadfence();
        unsigned prev = atomicAdd(&g_count, 1u);
        if (prev == gridDim.x - 1u) {
            g_count = 0u;                       // safe: waiters spin on sense
            __threadfence();
            *(volatile unsigned*)&g_sense = s;  // release
        } else {
            while (*(volatile unsigned*)&g_sense != s) __nanosleep(64);
        }
        __threadfence();                        // acquire + L1D invalidate
    }
    __syncthreads();
}

__global__ __launch_bounds__(NTHR, 1)
void k_fused(const float* __restrict__ J, const float* __restrict__ bias,
             const float* __restrict__ gat_W, const float* __restrict__ gat_a,
             const float* __restrict__ W1, const float* __restrict__ b1,
             const float* __restrict__ W2, const float* __restrict__ b2,
             const float* __restrict__ W3, const float* __restrict__ b3,
             const int* __restrict__ row, const int* __restrict__ col,
             const int* __restrict__ rev, const int* __restrict__ ru,
             const int* __restrict__ cu, const int* __restrict__ u2e,
             int N, int E, int Eu,
             float* __restrict__ out_readout, float* __restrict__ out_pw,
             float* __restrict__ out_scal, float* __restrict__ out_Ci,
             float* __restrict__ out_cij, float* __restrict__ out_dom)
{
    __shared__ float sW2[HID * HID];
    __shared__ float sh1[8][HID];
    __shared__ float sr[8][2][3];
    __shared__ float sred[NTHR];

    const int tid = threadIdx.x;
    const int b = blockIdx.x;
    const int gsize = NBLK * NTHR;
    unsigned lsense = 0u;

    // ================= P1: strided edge init (Jv gather, em0=0, CSR) =========
    for (int e = b * NTHR + tid; e < E; e += gsize) {
        int r = row[e];
        g_Jv[e] = J[(long long)r * N + col[e]];
        g_emA[2 * e] = 0.0f;
        g_emA[2 * e + 1] = 0.0f;
        if (e == 0 || row[e - 1] != r) g_start[r] = e;
        if (e == E - 1) g_start[N] = E;
    }
    grid_barrier(lsense);                                   // B1

    const int npb = (N + NBLK - 1) / NBLK;                  // 32 for N=4096
    const int n0 = b * npb;
    const int n1 = min(N, n0 + npb);

    // ================= P2: node features + GAT f1/f2 + Ci MLP ================
    for (int i = tid; i < HID * HID; i += NTHR) sW2[i] = W2[i];
    {
        int u = tid & 63;
        int nl8 = tid >> 6;                                 // 0..7
        const int npass = (npb + 7) / 8;
        for (int p = 0; p < npass; p++) {
            int node = n0 + p * 8 + nl8;
            int nc = node < n1 ? node : (n1 > 0 ? n1 - 1 : 0);
            float bb = bias[nc];
            int s0 = g_start[nc], s1 = g_start[nc + 1];
            float deg = (float)(s1 - s0);
            float Jsum = 0.0f;
            for (int k = s0; k < s1; k++) Jsum += g_Jv[k];
            float ft0 = -bb, ft1 = bb, ft2 = deg, ft3 = Jsum;
            float wh = ft0 * gat_W[u] + ft1 * gat_W[HID + u]
                     + ft2 * gat_W[2 * HID + u] + ft3 * gat_W[3 * HID + u];
            float c1 = wh * gat_a[u];
            float c2 = wh * gat_a[HID + u];
            float h1 = b1[u] + ft0 * W1[u] + ft1 * W1[HID + u]
                     + ft2 * W1[2 * HID + u] + ft3 * W1[3 * HID + u];
            h1 = fmaxf(h1, 0.0f);
            sh1[nl8][u] = h1;
            #pragma unroll
            for (int off = 16; off > 0; off >>= 1) {
                c1 += __shfl_down_sync(0xffffffffu, c1, off);
                c2 += __shfl_down_sync(0xffffffffu, c2, off);
            }
            int half = u >> 5;
            if ((u & 31) == 0) { sr[nl8][half][0] = c1; sr[nl8][half][1] = c2; }
            __syncthreads();                               // also covers sW2
            float h2 = b2[u];
            #pragma unroll 8
            for (int k = 0; k < HID; k++) h2 += sh1[nl8][k] * sW2[k * HID + u];
            h2 = fmaxf(h2, 0.0f);
            float cp = h2 * W3[u];
            #pragma unroll
            for (int off = 16; off > 0; off >>= 1)
                cp += __shfl_down_sync(0xffffffffu, cp, off);
            if ((u & 31) == 0) sr[nl8][half][2] = cp;
            __syncthreads();
            if (node < n1 && u == 0) {
                g_f1[node] = sr[nl8][0][0] + sr[nl8][1][0];
                g_f2[node] = sr[nl8][0][1] + sr[nl8][1][1];
                float Ci = sr[nl8][0][2] + sr[nl8][1][2] + b3[0];
                g_Ci[node] = Ci;
                out_Ci[node] = Ci;
            }
            __syncthreads();                               // sh1/sr reuse
        }
    }
    grid_barrier(lsense);                                   // B2 (f1/f2 global)

    // ================= P3: edge attention Cij + J/Cij (block-local edges) ====
    const int es = g_start[n0];
    const int ee = g_start[n1];
    for (int e = es + tid; e < ee; e += NTHR) {
        int r = row[e], c = col[e];
        float a = g_f1[r] + g_f2[c];
        float bb2 = g_f1[c] + g_f2[r];
        a = (a >= 0.0f) ? a : 0.2f * a;                     // leaky_relu 0.2
        bb2 = (bb2 >= 0.0f) ? bb2 : 0.2f * bb2;
        float cij = 0.5f * (expf(a) + expf(bb2));
        g_Cij[e] = cij;
        g_jc[e] = g_Jv[e] / cij;
    }
    __syncthreads();

    // ================= P4: node constants (registers) + initial update =======
    const int w = tid >> 5;
    const int lane = tid & 31;
    const int jn = n0 + 2 * w + (lane >> 4);                // 16 lanes per node
    const int kk = lane & 15;
    const bool nvalid = (jn < n1);
    float dom = 1.0f, bx0 = 0.0f, bx1 = 0.0f;
    float hid0 = 0.0f, hid1 = 0.0f;
    int inc_e = -1, s0j = 0, degj = 0;
    if (nvalid) {
        s0j = g_start[jn];
        degj = g_start[jn + 1] - s0j;
        if (kk < degj) inc_e = rev[s0j + kk];
    }
    if (nvalid && kk == 0) {
        float csum = 0.0f;
        for (int k = s0j; k < s0j + degj; k++) csum += g_Cij[k];
        float d = g_Ci[jn] + csum;
        float sgn = (d > 0.0f) ? 1.0f : ((d < 0.0f) ? -1.0f : 0.0f);
        dom = sgn * fmaxf(fabsf(d), 0.1f);
        float bs = bias[jn] / dom;
        bx0 = -bs; bx1 = bs;
        float lnZ = logf(expf(bx0) + expf(bx1));            // nm == 0 at step 0
        hid0 = bx0 - lnZ; hid1 = bx1 - lnZ;
        g_lnZ[jn] = lnZ;
        g_hidden[2 * jn] = hid0;
        g_hidden[2 * jn + 1] = hid1;
        out_dom[jn] = dom;
    }

    // hoist loop-invariant edge constants into registers
    int nmy = 0;
    int eIdx[MAXEPT], eRow[MAXEPT], eRev[MAXEPT];
    float eJc[MAXEPT], eC[MAXEPT];
    int efall = -1;
    for (int e = es + tid; e < ee; e += NTHR) {
        if (nmy < MAXEPT) {
            eIdx[nmy] = e; eRow[nmy] = row[e]; eRev[nmy] = rev[e];
            eJc[nmy] = g_jc[e]; eC[nmy] = g_Cij[e];
            nmy++;
        } else { efall = e; break; }
    }
    __syncthreads();   // hidden/lnZ written above, read by edge phase below

    // ================= P5: BP loop — 1 grid barrier per step ================
    for (int t = 0; t < NSTEP; t++) {
        const float* emIn  = (t & 1) ? g_emB : g_emA;
        float*       emOut = (t & 1) ? g_emA : g_emB;
        #pragma unroll
        for (int i = 0; i < MAXEPT; i++) {
            if (i < nmy) {
                int r = eRow[i], re = eRev[i];
                float lz = g_lnZ[r];
                float b0 = g_hidden[2 * r]     + lz - emIn[2 * re];
                float b1v = g_hidden[2 * r + 1] + lz - emIn[2 * re + 1];
                float jcv = eJc[i];
                float M00 = expf( jcv + b0);
                float M01 = expf(-jcv + b0);
                float M10 = expf(-jcv + b1v);
                float M11 = expf( jcv + b1v);
                float t0 = fmaxf(M00, M10);
                float t1 = fmaxf(M01, M11);
                float den = t0 + t1;
                emOut[2 * eIdx[i]]     = eC[i] * logf(t0 / den);
                emOut[2 * eIdx[i] + 1] = eC[i] * logf(t1 / den);
            }
        }
        for (int e = efall; e >= 0 && e < ee; e += NTHR) {   // generic fallback
            int r = row[e], re = rev[e];
            float lz = g_lnZ[r];
            float b0 = g_hidden[2 * r]     + lz - emIn[2 * re];
            float b1v = g_hidden[2 * r + 1] + lz - emIn[2 * re + 1];
            float jcv = g_jc[e];
            float M00 = expf( jcv + b0);
            float M01 = expf(-jcv + b0);
            float M10 = expf(-jcv + b1v);
            float M11 = expf( jcv + b1v);
            float t0 = fmaxf(M00, M10);
            float t1 = fmaxf(M01, M11);
            float den = t0 + t1;
            emOut[2 * e]     = g_Cij[e] * logf(t0 / den);
            emOut[2 * e + 1] = g_Cij[e] * logf(t1 / den);
        }
        grid_barrier(lsense);                               // Bstep (10 of these)

        // node update: 16-lane gather of incoming messages, shuffle-tree sum
        float m0 = 0.0f, m1 = 0.0f;
        if (nvalid && inc_e >= 0) {
            m0 = emOut[2 * inc_e];
            m1 = emOut[2 * inc_e + 1];
        }
        #pragma unroll
        for (int off = 8; off > 0; off >>= 1) {
            m0 += __shfl_xor_sync(0xffffffffu, m0, off);
            m1 += __shfl_xor_sync(0xffffffffu, m1, off);
        }
        if (nvalid && kk == 0) {
            for (int k = 16; k < degj; k++) {               // degree>16 fallback
                int e2 = rev[s0j + k];
                m0 += emOut[2 * e2];
                m1 += emOut[2 * e2 + 1];
            }
            float x0 = bx0 + m0 / dom;
            float x1 = bx1 + m1 / dom;
            float lnZ = logf(expf(x0) + expf(x1));
            hid0 = x0 - lnZ; hid1 = x1 - lnZ;
            g_lnZ[jn] = lnZ;
            g_hidden[2 * jn] = hid0;
            g_hidden[2 * jn + 1] = hid1;
        }
        __syncthreads();                                    // before next edge read
    }

    // ================= P6: readout + node entropy partials ===================
    float pnode = 0.0f;
    if (nvalid && kk == 0) {
        float r0 = expf(hid0), r1 = expf(hid1);
        out_readout[2 * jn] = r0;
        out_readout[2 * jn + 1] = r1;
        float nH = -(r0 * logf(r0 + 1e-16f) + r1 * logf(r1 + 1e-16f));
        pnode = g_Ci[jn] * nH;
    }
    if (tid < 64) sred[tid] = 0.0f;
    __syncthreads();
    if (nvalid && kk == 0 && (jn - n0) < 64) sred[jn - n0] = pnode;
    __syncthreads();
    if (tid == 0) {
        float s = 0.0f;
        for (int i2 = 0; i2 < npb && i2 < 64; i2++) s += sred[i2];
        g_npart[b] = s;
    }
    grid_barrier(lsense);                                   // B13 (readout global)

    // ================= P7: pairwise readout + edge entropy ==================
    // final messages: NSTEP even -> g_emA
    float pedge = 0.0f;
    for (int uu = b * NTHR + tid; uu < Eu; uu += gsize) {
        int e = u2e[uu];
        int er = rev[e];
        int ci = cu[uu], rj = ru[uu];
        float Js = g_jc[e];
        float ti0 = out_readout[2 * ci]     / expf(g_emA[2 * e]);
        float ti1 = out_readout[2 * ci + 1] / expf(g_emA[2 * e + 1]);
        float tj0 = out_readout[2 * rj]     / expf(g_emA[2 * er]);
        float tj1 = out_readout[2 * rj + 1] / expf(g_emA[2 * er + 1]);
        float eJ = expf(Js), eJm = expf(-Js);
        float p00 = eJ  * ti0 * tj0;
        float p01 = eJm * ti1 * tj0;
        float p10 = eJm * ti0 * tj1;
        float p11 = eJ  * ti1 * tj1;
        float S = p00 + p01 + p10 + p11;
        float q00 = p00 / S, q01 = p01 / S, q10 = p10 / S, q11 = p11 / S;
        out_pw[4 * uu]     = q00;
        out_pw[4 * uu + 1] = q01;
        out_pw[4 * uu + 2] = q10;
        out_pw[4 * uu + 3] = q11;
        float Cu = g_Cij[e];
        out_cij[uu] = Cu;
        float eH = -(q00 * logf(q00 + 1e-16f) + q01 * logf(q01 + 1e-16f)
                   + q10 * logf(q10 + 1e-16f) + q11 * logf(q11 + 1e-16f));
        pedge += Cu * eH;
    }
    sred[tid] = pedge;
    __syncthreads();
    #pragma unroll
    for (int off = NTHR / 2; off > 0; off >>= 1) {
        if (tid < off) sred[tid] += sred[tid + off];
        __syncthreads();
    }
    if (tid == 0) g_epart[b] = sred[0];
    grid_barrier(lsense);                                   // B14 (even total!)

    // ================= P8: final deterministic scalars =======================
    if (b == 0 && tid == 0) {
        float ne = 0.0f, ed = 0.0f;
        for (int i2 = 0; i2 < NBLK; i2++) ne += g_npart[i2];
        for (int i2 = 0; i2 < NBLK; i2++) ed += g_epart[i2];
        out_scal[0] = ne + ed;
        out_scal[1] = ne;
        out_scal[2] = ed;
    }
}

// ---------------- launcher ---------------------------------------------------
extern "C" void kernel_launch(void* const* d_in, const int* in_sizes, int n_in,
                              void* d_out, int out_size) {
    const float* J     = (const float*)d_in[0];
    const float* bias  = (const float*)d_in[1];
    const float* gat_W = (const float*)d_in[2];
    const float* gat_a = (const float*)d_in[3];
    const float* W1    = (const float*)d_in[4];
    const float* b1    = (const float*)d_in[5];
    const float* W2    = (const float*)d_in[6];
    const float* b2    = (const float*)d_in[7];
    const float* W3    = (const float*)d_in[8];
    const float* b3    = (const float*)d_in[9];
    const int*   row   = (const int*)d_in[10];
    const int*   col   = (const int*)d_in[11];
    const int*   rev   = (const int*)d_in[12];
    const int*   ru    = (const int*)d_in[13];
    const int*   cu    = (const int*)d_in[14];
    const int*   u2e   = (const int*)d_in[15];

    int N  = in_sizes[1];
    int E  = in_sizes[10];
    int Eu = in_sizes[13];

    float* out = (float*)d_out;
    float* out_readout = out;                    // [N,2]
    float* out_pw      = out + 2 * N;            // [Eu,4]
    float* out_scal    = out + 2 * N + 4 * Eu;   // 3 scalars
    float* out_Ci      = out_scal + 3;           // [N]
    float* out_cij     = out_Ci + N;             // [Eu]
    float* out_dom     = out_cij + Eu;           // [N]

    k_fused<<<NBLK, NTHR>>>(J, bias, gat_W, gat_a, W1, b1, W2, b2, W3, b3,
                            row, col, rev, ru, cu, u2e, N, E, Eu,
                            out_readout, out_pw, out_scal, out_Ci, out_cij,
                            out_dom);
}

// round 6
// speedup vs baseline: 2.0757x; 1.1652x over previous
#include <cuda_runtime.h>
#include <math.h>

#define HID 64
#define NMAX 8192
#define EMAX 131072
#define NBLK 128
#define NTHR 512
#define NSTEP 10

// ---------------- device scratch (no allocation allowed) ----------------
__device__ float g_Jv[EMAX];
__device__ float g_Cij[EMAX];
__device__ float g_jc[EMAX];
__device__ float g_em[2 * EMAX];     // final messages (dumped post-loop)
__device__ float g_f1[NMAX];
__device__ float g_f2[NMAX];
__device__ float g_Ci[NMAX];
__device__ float g_x[2 * NMAX];      // x = bx + nm/dom (the only per-step global)
__device__ int   g_start[NMAX + 1];
__device__ float g_npart[NBLK];
__device__ float g_epart[NBLK];
__device__ unsigned g_count;         // returns to 0 after every barrier
__device__ unsigned g_sense;         // lsense derived from it -> parity-safe

// Sense-reversal grid barrier. gpu-scope __threadfence emits CCTL.IVALL on
// sm_103a -> L1D flushed, so plain loads after the barrier see remote writes.
__device__ __forceinline__ void grid_barrier(unsigned& lsense) {
    __syncthreads();
    if (threadIdx.x == 0) {
        unsigned s = lsense ^ 1u;
        lsense = s;
        __threadfence();
        unsigned prev = atomicAdd(&g_count, 1u);
        if (prev == gridDim.x - 1u) {
            g_count = 0u;                       // safe: waiters spin on sense
            __threadfence();
            *(volatile unsigned*)&g_sense = s;  // release
        } else {
            while (*(volatile unsigned*)&g_sense != s) __nanosleep(32);
        }
        __threadfence();                        // acquire + L1D invalidate
    }
    __syncthreads();
}

__global__ __launch_bounds__(NTHR, 1)
void k_fused(const float* __restrict__ J, const float* __restrict__ bias,
             const float* __restrict__ gat_W, const float* __restrict__ gat_a,
             const float* __restrict__ W1, const float* __restrict__ b1,
             const float* __restrict__ W2, const float* __restrict__ b2,
             const float* __restrict__ W3, const float* __restrict__ b3,
             const int* __restrict__ row, const int* __restrict__ col,
             const int* __restrict__ rev, const int* __restrict__ ru,
             const int* __restrict__ cu, const int* __restrict__ u2e,
             int N, int E, int Eu,
             float* __restrict__ out_readout, float* __restrict__ out_pw,
             float* __restrict__ out_scal, float* __restrict__ out_Ci,
             float* __restrict__ out_cij, float* __restrict__ out_dom)
{
    __shared__ float sW2[HID * HID];
    __shared__ float sh1[8][HID];
    __shared__ float sr[8][2][3];
    __shared__ float sred[NTHR];

    const int tid = threadIdx.x;
    const int b = blockIdx.x;
    const int gsize = NBLK * NTHR;
    unsigned lsense = *(volatile unsigned*)&g_sense;  // stable between launches

    // ================= P1: edge init (Jv gather, CSR starts) =================
    for (int e = b * NTHR + tid; e < E; e += gsize) {
        int r = row[e];
        g_Jv[e] = J[(long long)r * N + col[e]];
        if (e == 0 || row[e - 1] != r) g_start[r] = e;
        if (e == E - 1) g_start[N] = E;
    }
    grid_barrier(lsense);                                   // B1

    const int npb = (N + NBLK - 1) / NBLK;                  // 32 for N=4096
    const int n0 = b * npb;
    const int n1 = min(N, n0 + npb);

    // ================= P2: node features + GAT f1/f2 + Ci MLP ================
    for (int i = tid; i < HID * HID; i += NTHR) sW2[i] = W2[i];
    {
        int u = tid & 63;
        int nl8 = tid >> 6;
        const int npass = (npb + 7) / 8;
        for (int p = 0; p < npass; p++) {
            int node = n0 + p * 8 + nl8;
            int nc = node < n1 ? node : (n1 > 0 ? n1 - 1 : 0);
            float bb = bias[nc];
            int s0 = g_start[nc], s1 = g_start[nc + 1];
            float deg = (float)(s1 - s0);
            float Jsum = 0.0f;
            for (int k2 = s0; k2 < s1; k2++) Jsum += g_Jv[k2];
            float ft0 = -bb, ft1 = bb, ft2 = deg, ft3 = Jsum;
            float wh = ft0 * gat_W[u] + ft1 * gat_W[HID + u]
                     + ft2 * gat_W[2 * HID + u] + ft3 * gat_W[3 * HID + u];
            float c1 = wh * gat_a[u];
            float c2 = wh * gat_a[HID + u];
            float h1 = b1[u] + ft0 * W1[u] + ft1 * W1[HID + u]
                     + ft2 * W1[2 * HID + u] + ft3 * W1[3 * HID + u];
            h1 = fmaxf(h1, 0.0f);
            sh1[nl8][u] = h1;
            #pragma unroll
            for (int off = 16; off > 0; off >>= 1) {
                c1 += __shfl_down_sync(0xffffffffu, c1, off);
                c2 += __shfl_down_sync(0xffffffffu, c2, off);
            }
            int half = u >> 5;
            if ((u & 31) == 0) { sr[nl8][half][0] = c1; sr[nl8][half][1] = c2; }
            __syncthreads();
            float h2 = b2[u];
            #pragma unroll 8
            for (int k2 = 0; k2 < HID; k2++) h2 += sh1[nl8][k2] * sW2[k2 * HID + u];
            h2 = fmaxf(h2, 0.0f);
            float cp = h2 * W3[u];
            #pragma unroll
            for (int off = 16; off > 0; off >>= 1)
                cp += __shfl_down_sync(0xffffffffu, cp, off);
            if ((u & 31) == 0) sr[nl8][half][2] = cp;
            __syncthreads();
            if (node < n1 && u == 0) {
                g_f1[node] = sr[nl8][0][0] + sr[nl8][1][0];
                g_f2[node] = sr[nl8][0][1] + sr[nl8][1][1];
                float Ci = sr[nl8][0][2] + sr[nl8][1][2] + b3[0];
                g_Ci[node] = Ci;
                out_Ci[node] = Ci;
            }
            __syncthreads();
        }
    }
    grid_barrier(lsense);                                   // B2 (f1/f2 global)

    // ================= P3: per-thread edge/node constants + x init ===========
    // thread (jl, k): node jn = n0+jl owns incident undirected edge slot k.
    const int jl = tid >> 4;
    const int k = tid & 15;
    const int jn = n0 + jl;
    const bool nv = (jl < npb) && (jn < N);
    int s0j = 0, degj = 0, e_out = 0, i_nb = 0;
    if (nv) { s0j = g_start[jn]; degj = g_start[jn + 1] - s0j; }
    const bool ev = nv && (k < degj);
    float jc = 0.0f, C = 0.0f;
    if (ev) {
        e_out = s0j + k;                  // directed edge (jn -> i_nb)
        i_nb = col[e_out];
        float a = g_f1[jn] + g_f2[i_nb];
        float bb = g_f1[i_nb] + g_f2[jn];
        a = (a >= 0.0f) ? a : 0.2f * a;   // leaky_relu 0.2
        bb = (bb >= 0.0f) ? bb : 0.2f * bb;
        C = 0.5f * (expf(a) + expf(bb));  // symmetric: same both directions
        jc = g_Jv[e_out] / C;
        g_Cij[e_out] = C;
        g_jc[e_out] = jc;
    }
    // dom = clamp(Ci + sum_k Cij); all 16 lanes compute identically
    float csum = ev ? C : 0.0f;
    #pragma unroll
    for (int off = 8; off > 0; off >>= 1)
        csum += __shfl_xor_sync(0xffffffffu, csum, off);
    float dom = 1.0f, bx0 = 0.0f, bx1 = 0.0f, x0 = 0.0f, x1 = 0.0f;
    if (nv) {
        float d = g_Ci[jn] + csum;
        float sgn = (d > 0.0f) ? 1.0f : ((d < 0.0f) ? -1.0f : 0.0f);
        dom = sgn * fmaxf(fabsf(d), 0.1f);
        float bs = bias[jn] / dom;
        bx0 = -bs; bx1 = bs;
        x0 = bx0; x1 = bx1;               // em0 = 0 -> nm = 0
        if (k == 0) {
            g_x[2 * jn] = x0;
            g_x[2 * jn + 1] = x1;
            out_dom[jn] = dom;
        }
    }
    float ei0 = 0.0f, ei1 = 0.0f;         // em on in-edge  (i_nb -> jn)
    float eo0 = 0.0f, eo1 = 0.0f;         // em on out-edge (jn -> i_nb)
    grid_barrier(lsense);                                   // B3 (x global)

    // ================= P4: BP loop — all messages in registers ==============
    for (int t = 0; t < NSTEP; t++) {
        float ni0 = 0.0f, ni1 = 0.0f;
        if (ev) {
            float xi0 = g_x[2 * i_nb];    // only remote data per step
            float xi1 = g_x[2 * i_nb + 1];
            // out-message (jn->i): uses x_j and old in-message
            float b0 = x0 - ei0;
            float b1v = x1 - ei1;
            float M00 = expf( jc + b0);
            float M01 = expf(-jc + b0);
            float M10 = expf(-jc + b1v);
            float M11 = expf( jc + b1v);
            float t0 = fmaxf(M00, M10);
            float t1 = fmaxf(M01, M11);
            float den = t0 + t1;
            float no0 = C * logf(t0 / den);
            float no1 = C * logf(t1 / den);
            // in-message (i->jn): uses x_i and old out-message
            float c0 = xi0 - eo0;
            float c1 = xi1 - eo1;
            float P00 = expf( jc + c0);
            float P01 = expf(-jc + c0);
            float P10 = expf(-jc + c1);
            float P11 = expf( jc + c1);
            float s0m = fmaxf(P00, P10);
            float s1m = fmaxf(P01, P11);
            float den2 = s0m + s1m;
            ni0 = C * logf(s0m / den2);
            ni1 = C * logf(s1m / den2);
            eo0 = no0; eo1 = no1;
            ei0 = ni0; ei1 = ni1;
        }
        // node update: sum in-messages over 16 lanes (xor tree), all lanes get x
        float m0 = ni0, m1 = ni1;
        #pragma unroll
        for (int off = 8; off > 0; off >>= 1) {
            m0 += __shfl_xor_sync(0xffffffffu, m0, off);
            m1 += __shfl_xor_sync(0xffffffffu, m1, off);
        }
        if (nv) {
            x0 = bx0 + m0 / dom;
            x1 = bx1 + m1 / dom;
            if (k == 0 && t != NSTEP - 1) {
                g_x[2 * jn] = x0;
                g_x[2 * jn + 1] = x1;
            }
        }
        if (t != NSTEP - 1) grid_barrier(lsense);           // 9 in-loop barriers
    }

    // ================= P5: dump messages + readout + node entropy ===========
    if (ev) {
        g_em[2 * e_out] = eo0;            // out-edges cover all E exactly once
        g_em[2 * e_out + 1] = eo1;
    }
    float pnode = 0.0f;
    if (nv && k == 0) {
        float lnZ = logf(expf(x0) + expf(x1));
        float r0 = expf(x0 - lnZ);
        float r1 = expf(x1 - lnZ);
        out_readout[2 * jn] = r0;
        out_readout[2 * jn + 1] = r1;
        float nH = -(r0 * logf(r0 + 1e-16f) + r1 * logf(r1 + 1e-16f));
        pnode = g_Ci[jn] * nH;
    }
    if (tid < 32) sred[tid] = 0.0f;
    __syncthreads();
    if (nv && k == 0 && jl < 32) sred[jl] = pnode;
    __syncthreads();
    if (tid == 0) {
        float s = 0.0f;
        for (int i2 = 0; i2 < npb && i2 < 32; i2++) s += sred[i2];
        g_npart[b] = s;
    }
    grid_barrier(lsense);                                   // B13

    // ================= P6: pairwise readout + edge entropy ==================
    float pedge = 0.0f;
    for (int uu = b * NTHR + tid; uu < Eu; uu += gsize) {
        int e = u2e[uu];
        int er = rev[e];
        int ci = cu[uu], rj = ru[uu];
        float Js = g_jc[e];
        float ti0 = out_readout[2 * ci]     / expf(g_em[2 * e]);
        float ti1 = out_readout[2 * ci + 1] / expf(g_em[2 * e + 1]);
        float tj0 = out_readout[2 * rj]     / expf(g_em[2 * er]);
        float tj1 = out_readout[2 * rj + 1] / expf(g_em[2 * er + 1]);
        float eJ = expf(Js), eJm = expf(-Js);
        float p00 = eJ  * ti0 * tj0;
        float p01 = eJm * ti1 * tj0;
        float p10 = eJm * ti0 * tj1;
        float p11 = eJ  * ti1 * tj1;
        float S = p00 + p01 + p10 + p11;
        float q00 = p00 / S, q01 = p01 / S, q10 = p10 / S, q11 = p11 / S;
        out_pw[4 * uu]     = q00;
        out_pw[4 * uu + 1] = q01;
        out_pw[4 * uu + 2] = q10;
        out_pw[4 * uu + 3] = q11;
        float Cu = g_Cij[e];
        out_cij[uu] = Cu;
        float eH = -(q00 * logf(q00 + 1e-16f) + q01 * logf(q01 + 1e-16f)
                   + q10 * logf(q10 + 1e-16f) + q11 * logf(q11 + 1e-16f));
        pedge += Cu * eH;
    }
    sred[tid] = pedge;
    __syncthreads();
    #pragma unroll
    for (int off = NTHR / 2; off > 0; off >>= 1) {
        if (tid < off) sred[tid] += sred[tid + off];
        __syncthreads();
    }
    if (tid == 0) g_epart[b] = sred[0];
    grid_barrier(lsense);                                   // B14

    // ================= P7: final deterministic scalars ======================
    if (b == 0 && tid == 0) {
        float ne = 0.0f, ed = 0.0f;
        for (int i2 = 0; i2 < NBLK; i2++) ne += g_npart[i2];
        for (int i2 = 0; i2 < NBLK; i2++) ed += g_epart[i2];
        out_scal[0] = ne + ed;
        out_scal[1] = ne;
        out_scal[2] = ed;
    }
}

// ---------------- launcher ---------------------------------------------------
extern "C" void kernel_launch(void* const* d_in, const int* in_sizes, int n_in,
                              void* d_out, int out_size) {
    const float* J     = (const float*)d_in[0];
    const float* bias  = (const float*)d_in[1];
    const float* gat_W = (const float*)d_in[2];
    const float* gat_a = (const float*)d_in[3];
    const float* W1    = (const float*)d_in[4];
    const float* b1    = (const float*)d_in[5];
    const float* W2    = (const float*)d_in[6];
    const float* b2    = (const float*)d_in[7];
    const float* W3    = (const float*)d_in[8];
    const float* b3    = (const float*)d_in[9];
    const int*   row   = (const int*)d_in[10];
    const int*   col   = (const int*)d_in[11];
    const int*   rev   = (const int*)d_in[12];
    const int*   ru    = (const int*)d_in[13];
    const int*   cu    = (const int*)d_in[14];
    const int*   u2e   = (const int*)d_in[15];

    int N  = in_sizes[1];
    int E  = in_sizes[10];
    int Eu = in_sizes[13];

    float* out = (float*)d_out;
    float* out_readout = out;                    // [N,2]
    float* out_pw      = out + 2 * N;            // [Eu,4]
    float* out_scal    = out + 2 * N + 4 * Eu;   // 3 scalars
    float* out_Ci      = out_scal + 3;           // [N]
    float* out_cij     = out_Ci + N;             // [Eu]
    float* out_dom     = out_cij + Eu;           // [N]

    k_fused<<<NBLK, NTHR>>>(J, bias, gat_W, gat_a, W1, b1, W2, b2, W3, b3,
                            row, col, rev, ru, cu, u2e, N, E, Eu,
                            out_readout, out_pw, out_scal, out_Ci, out_cij,
                            out_dom);
}

// round 7
// speedup vs baseline: 2.5298x; 1.2187x over previous
#include <cuda_runtime.h>
#include <math.h>

#define HID 64
#define NMAX 8192
#define EMAX 131072
#define NBLK 128
#define NTHR 512
#define NSTEP 10

// ---------------- device scratch (no allocation allowed) ----------------
__device__ float  g_Jv[EMAX];
__device__ float  g_Cij[EMAX];
__device__ float  g_jc[EMAX];
__device__ float2 g_em2[EMAX];      // final messages (dumped post-loop)
__device__ float  g_f1[NMAX];
__device__ float  g_f2[NMAX];
__device__ float  g_Ci[NMAX];
__device__ float2 g_x2[NMAX];       // x = bx + nm/dom (the only per-step global)
__device__ float  g_npart[NBLK];
__device__ float  g_epart[NBLK];
__device__ unsigned g_count;        // returns to 0 after every barrier
__device__ unsigned g_sense;        // lsense derived at entry -> parity-safe
__device__ unsigned g_done;         // last-block finalize counter (reset per launch)

// Fence-light sense-reversal barrier: release-atomic arrival, acquire-load
// spin. NO __threadfence / CCTL.IVALL — all cross-block data reads after a
// barrier go through __ldcg (L2 = coherence point; ldcg never hits stale L1).
__device__ __forceinline__ void grid_barrier(unsigned& lsense) {
    __syncthreads();
    if (threadIdx.x == 0) {
        unsigned s = lsense ^ 1u;
        lsense = s;
        unsigned prev;
        asm volatile("atom.release.gpu.add.u32 %0, [%1], %2;"
                     : "=r"(prev) : "l"(&g_count), "r"(1u) : "memory");
        if (prev == gridDim.x - 1u) {
            g_count = 0u;   // ordered before release store below
            asm volatile("st.release.gpu.u32 [%0], %1;"
                         :: "l"(&g_sense), "r"(s) : "memory");
        } else {
            unsigned v;
            do {
                asm volatile("ld.acquire.gpu.u32 %0, [%1];"
                             : "=r"(v) : "l"(&g_sense) : "memory");
                if (v == s) break;
                __nanosleep(32);
            } while (true);
        }
    }
    __syncthreads();
}

__global__ __launch_bounds__(NTHR, 1)
void k_fused(const float* __restrict__ J, const float* __restrict__ bias,
             const float* __restrict__ gat_W, const float* __restrict__ gat_a,
             const float* __restrict__ W1, const float* __restrict__ b1,
             const float* __restrict__ W2, const float* __restrict__ b2,
             const float* __restrict__ W3, const float* __restrict__ b3,
             const int* __restrict__ row, const int* __restrict__ col,
             const int* __restrict__ rev, const int* __restrict__ ru,
             const int* __restrict__ cu, const int* __restrict__ u2e,
             int N, int E, int Eu,
             float* __restrict__ out_readout, float* __restrict__ out_pw,
             float* __restrict__ out_scal, float* __restrict__ out_Ci,
             float* __restrict__ out_cij, float* __restrict__ out_dom)
{
    __shared__ float sW2[HID * HID];
    __shared__ float sh1[8][HID];
    __shared__ float sr[8][2][3];
    __shared__ float sred[NTHR];

    const int tid = threadIdx.x;
    const int b = blockIdx.x;
    const int gsize = NBLK * NTHR;
    const int DEG = E / N;                    // uniform degree (16)
    unsigned lsense;
    asm volatile("ld.acquire.gpu.u32 %0, [%1];" : "=r"(lsense) : "l"(&g_sense));

    const int npb = (N + NBLK - 1) / NBLK;    // 32
    const int n0 = b * npb;
    const int n1 = min(N, n0 + npb);
    const int es = n0 * DEG;                  // own edge chunk (arithmetic CSR)
    const int ee = n1 * DEG;

    // ===== P1: own-chunk Jv gather (self-written, self-read -> no grid bar) ==
    for (int e = es + tid; e < ee; e += NTHR) {
        int r = e / DEG;
        g_Jv[e] = J[(long long)r * N + col[e]];
    }
    __syncthreads();

    // ===== P2: node features + GAT f1/f2 + Ci MLP ============================
    for (int i = tid; i < HID * HID; i += NTHR) sW2[i] = W2[i];
    {
        int u = tid & 63;
        int nl8 = tid >> 6;
        const int npass = (npb + 7) / 8;
        for (int p = 0; p < npass; p++) {
            int node = n0 + p * 8 + nl8;
            int nc = node < n1 ? node : (n1 > 0 ? n1 - 1 : 0);
            float bb = bias[nc];
            int s0 = nc * DEG;
            float Jsum = 0.0f;
            for (int k2 = 0; k2 < DEG; k2++) Jsum += g_Jv[s0 + k2];
            float ft0 = -bb, ft1 = bb, ft2 = (float)DEG, ft3 = Jsum;
            float wh = ft0 * gat_W[u] + ft1 * gat_W[HID + u]
                     + ft2 * gat_W[2 * HID + u] + ft3 * gat_W[3 * HID + u];
            float c1 = wh * gat_a[u];
            float c2 = wh * gat_a[HID + u];
            float h1 = b1[u] + ft0 * W1[u] + ft1 * W1[HID + u]
                     + ft2 * W1[2 * HID + u] + ft3 * W1[3 * HID + u];
            h1 = fmaxf(h1, 0.0f);
            sh1[nl8][u] = h1;
            #pragma unroll
            for (int off = 16; off > 0; off >>= 1) {
                c1 += __shfl_down_sync(0xffffffffu, c1, off);
                c2 += __shfl_down_sync(0xffffffffu, c2, off);
            }
            int half = u >> 5;
            if ((u & 31) == 0) { sr[nl8][half][0] = c1; sr[nl8][half][1] = c2; }
            __syncthreads();
            float h2 = b2[u];
            #pragma unroll 8
            for (int k2 = 0; k2 < HID; k2++) h2 += sh1[nl8][k2] * sW2[k2 * HID + u];
            h2 = fmaxf(h2, 0.0f);
            float cp = h2 * W3[u];
            #pragma unroll
            for (int off = 16; off > 0; off >>= 1)
                cp += __shfl_down_sync(0xffffffffu, cp, off);
            if ((u & 31) == 0) sr[nl8][half][2] = cp;
            __syncthreads();
            if (node < n1 && u == 0) {
                g_f1[node] = sr[nl8][0][0] + sr[nl8][1][0];
                g_f2[node] = sr[nl8][0][1] + sr[nl8][1][1];
                float Ci = sr[nl8][0][2] + sr[nl8][1][2] + b3[0];
                g_Ci[node] = Ci;
                out_Ci[node] = Ci;
            }
            __syncthreads();
        }
    }
    grid_barrier(lsense);                                   // B-A (f1/f2 global)

    // ===== P3: per-thread edge/node constants + x init =======================
    const int jl = tid >> 4;
    const int k = tid & 15;
    const int jn = n0 + jl;
    const bool nv = (jl < npb) && (jn < n1);
    const bool ev = nv && (k < DEG);
    int e_out = 0, i_nb = 0;
    float jc = 0.0f, C = 0.0f;
    if (ev) {
        e_out = jn * DEG + k;                 // directed edge (jn -> i_nb)
        i_nb = col[e_out];
        float f1j = __ldcg(&g_f1[jn]);
        float f2j = __ldcg(&g_f2[jn]);
        float f1i = __ldcg(&g_f1[i_nb]);
        float f2i = __ldcg(&g_f2[i_nb]);
        float a = f1j + f2i;
        float bb = f1i + f2j;
        a = (a >= 0.0f) ? a : 0.2f * a;       // leaky_relu 0.2
        bb = (bb >= 0.0f) ? bb : 0.2f * bb;
        C = 0.5f * (__expf(a) + __expf(bb));  // symmetric both directions
        jc = g_Jv[e_out] / C;
        g_Cij[e_out] = C;
        g_jc[e_out] = jc;
    }
    float csum = ev ? C : 0.0f;
    #pragma unroll
    for (int off = 8; off > 0; off >>= 1)
        csum += __shfl_xor_sync(0xffffffffu, csum, off);
    float dom = 1.0f, rdom = 1.0f, bx0 = 0.0f, bx1 = 0.0f, x0 = 0.0f, x1 = 0.0f;
    if (nv) {
        float d = g_Ci[jn] + csum;
        float sgn = (d > 0.0f) ? 1.0f : ((d < 0.0f) ? -1.0f : 0.0f);
        dom = sgn * fmaxf(fabsf(d), 0.1f);
        rdom = 1.0f / dom;
        float bs = bias[jn] * rdom;
        bx0 = -bs; bx1 = bs;
        x0 = bx0; x1 = bx1;                   // em0 = 0 -> nm = 0
        if (k == 0) {
            g_x2[jn] = make_float2(x0, x1);
            out_dom[jn] = dom;
        }
    }
    const float ejc  = __expf(jc);            // loop-invariant
    const float ejcm = __expf(-jc);
    float ei0 = 0.0f, ei1 = 0.0f;             // em on in-edge  (i_nb -> jn)
    float eo0 = 0.0f, eo1 = 0.0f;             // em on out-edge (jn -> i_nb)
    grid_barrier(lsense);                                   // B-B (x global)

    // ===== P4: BP loop — all messages in registers, fast transcendentals =====
    for (int t = 0; t < NSTEP; t++) {
        float ni0 = 0.0f, ni1 = 0.0f;
        if (ev) {
            float2 xi = __ldcg(&g_x2[i_nb]);  // only remote data per step
            // out-message (jn->i): x_j and old in-message
            float eb0 = __expf(x0 - ei0);
            float eb1 = __expf(x1 - ei1);
            float t0 = fmaxf(ejc * eb0, ejcm * eb1);
            float t1 = fmaxf(ejcm * eb0, ejc * eb1);
            float inv = __frcp_rn(t0 + t1);
            float no0 = C * __logf(t0 * inv);
            float no1 = C * __logf(t1 * inv);
            // in-message (i->jn): x_i and old out-message
            float ec0 = __expf(xi.x - eo0);
            float ec1 = __expf(xi.y - eo1);
            float s0m = fmaxf(ejc * ec0, ejcm * ec1);
            float s1m = fmaxf(ejcm * ec0, ejc * ec1);
            float inv2 = __frcp_rn(s0m + s1m);
            ni0 = C * __logf(s0m * inv2);
            ni1 = C * __logf(s1m * inv2);
            eo0 = no0; eo1 = no1;
            ei0 = ni0; ei1 = ni1;
        }
        // node update: xor-tree over the node's 16 lanes
        float m0 = ni0, m1 = ni1;
        #pragma unroll
        for (int off = 8; off > 0; off >>= 1) {
            m0 += __shfl_xor_sync(0xffffffffu, m0, off);
            m1 += __shfl_xor_sync(0xffffffffu, m1, off);
        }
        if (nv) {
            x0 = bx0 + m0 * rdom;
            x1 = bx1 + m1 * rdom;
            if (k == 0 && t != NSTEP - 1) g_x2[jn] = make_float2(x0, x1);
        }
        if (t != NSTEP - 1) grid_barrier(lsense);           // 9 in-loop barriers
    }

    // ===== P5: dump messages + readout + node entropy partials ==============
    if (ev) g_em2[e_out] = make_float2(eo0, eo1);
    float pnode = 0.0f;
    if (nv && k == 0) {
        float e0 = __expf(x0), e1 = __expf(x1);
        float inv = __frcp_rn(e0 + e1);
        float r0 = e0 * inv, r1 = e1 * inv;
        out_readout[2 * jn] = r0;
        out_readout[2 * jn + 1] = r1;
        float nH = -(r0 * __logf(r0 + 1e-16f) + r1 * __logf(r1 + 1e-16f));
        pnode = g_Ci[jn] * nH;
    }
    if (tid < 32) sred[tid] = 0.0f;
    __syncthreads();
    if (nv && k == 0 && jl < 32) sred[jl] = pnode;
    __syncthreads();
    if (tid == 0) {
        float s = 0.0f;
        for (int i2 = 0; i2 < npb && i2 < 32; i2++) s += sred[i2];
        g_npart[b] = s;
    }
    grid_barrier(lsense);                                   // B-L (em/readout global)

    // ===== P6: pairwise readout + edge entropy ==============================
    float pedge = 0.0f;
    for (int uu = b * NTHR + tid; uu < Eu; uu += gsize) {
        int e = u2e[uu];
        int er = rev[e];
        int ci = cu[uu], rj = ru[uu];
        float Js = __ldcg(&g_jc[e]);
        float Cu = __ldcg(&g_Cij[e]);
        float2 eme = __ldcg(&g_em2[e]);
        float2 emr = __ldcg(&g_em2[er]);
        float2 rci = __ldcg((const float2*)(out_readout + 2 * ci));
        float2 rrj = __ldcg((const float2*)(out_readout + 2 * rj));
        float ti0 = rci.x * __expf(-eme.x);
        float ti1 = rci.y * __expf(-eme.y);
        float tj0 = rrj.x * __expf(-emr.x);
        float tj1 = rrj.y * __expf(-emr.y);
        float eJ = __expf(Js), eJm = __expf(-Js);
        float p00 = eJ  * ti0 * tj0;
        float p01 = eJm * ti1 * tj0;
        float p10 = eJm * ti0 * tj1;
        float p11 = eJ  * ti1 * tj1;
        float invS = __frcp_rn(p00 + p01 + p10 + p11);
        float q00 = p00 * invS, q01 = p01 * invS;
        float q10 = p10 * invS, q11 = p11 * invS;
        out_pw[4 * uu]     = q00;
        out_pw[4 * uu + 1] = q01;
        out_pw[4 * uu + 2] = q10;
        out_pw[4 * uu + 3] = q11;
        out_cij[uu] = Cu;
        float eH = -(q00 * __logf(q00 + 1e-16f) + q01 * __logf(q01 + 1e-16f)
                   + q10 * __logf(q10 + 1e-16f) + q11 * __logf(q11 + 1e-16f));
        pedge += Cu * eH;
    }
    sred[tid] = pedge;
    __syncthreads();
    #pragma unroll
    for (int off = NTHR / 2; off > 0; off >>= 1) {
        if (tid < off) sred[tid] += sred[tid + off];
        __syncthreads();
    }

    // ===== P7: last-arriving block finalizes scalars (no extra barrier) =====
    if (tid == 0) {
        g_epart[b] = sred[0];
        unsigned prev;
        asm volatile("atom.acq_rel.gpu.add.u32 %0, [%1], %2;"
                     : "=r"(prev) : "l"(&g_done), "r"(1u) : "memory");
        if (prev == (unsigned)(NBLK - 1)) {
            float ne = 0.0f, ed = 0.0f;
            for (int i2 = 0; i2 < NBLK; i2++) ne += __ldcg(&g_npart[i2]);
            for (int i2 = 0; i2 < NBLK; i2++) ed += __ldcg(&g_epart[i2]);
            out_scal[0] = ne + ed;
            out_scal[1] = ne;
            out_scal[2] = ed;
            g_done = 0u;     // reset for next graph replay (flushed at kernel end)
        }
    }
}

// ---------------- launcher ---------------------------------------------------
extern "C" void kernel_launch(void* const* d_in, const int* in_sizes, int n_in,
                              void* d_out, int out_size) {
    const float* J     = (const float*)d_in[0];
    const float* bias  = (const float*)d_in[1];
    const float* gat_W = (const float*)d_in[2];
    const float* gat_a = (const float*)d_in[3];
    const float* W1    = (const float*)d_in[4];
    const float* b1    = (const float*)d_in[5];
    const float* W2    = (const float*)d_in[6];
    const float* b2    = (const float*)d_in[7];
    const float* W3    = (const float*)d_in[8];
    const float* b3    = (const float*)d_in[9];
    const int*   row   = (const int*)d_in[10];
    const int*   col   = (const int*)d_in[11];
    const int*   rev   = (const int*)d_in[12];
    const int*   ru    = (const int*)d_in[13];
    const int*   cu    = (const int*)d_in[14];
    const int*   u2e   = (const int*)d_in[15];

    int N  = in_sizes[1];
    int E  = in_sizes[10];
    int Eu = in_sizes[13];

    float* out = (float*)d_out;
    float* out_readout = out;                    // [N,2]
    float* out_pw      = out + 2 * N;            // [Eu,4]
    float* out_scal    = out + 2 * N + 4 * Eu;   // 3 scalars
    float* out_Ci      = out_scal + 3;           // [N]
    float* out_cij     = out_Ci + N;             // [Eu]
    float* out_dom     = out_cij + Eu;           // [N]

    k_fused<<<NBLK, NTHR>>>(J, bias, gat_W, gat_a, W1, b1, W2, b2, W3, b3,
                            row, col, rev, ru, cu, u2e, N, E, Eu,
                            out_readout, out_pw, out_scal, out_Ci, out_cij,
                            out_dom);
}